// round 1
// baseline (speedup 1.0000x reference)
#include <cuda_runtime.h>
#include <math.h>

#define V 50257
#define H 1024
#define T 10

// ---------------- device scratch (no allocations allowed) ----------------
__device__ __align__(16) float g_h[2][H];
__device__ __align__(16) float g_c[2][H];
__device__ __align__(16) float g_enc[T * H];   // encoder outputs (T, H)
__device__ __align__(16) float g_prev[H];      // greedy feedback embedding
__device__ __align__(16) float g_q[H];         // h @ wa
__device__ __align__(16) float g_ctx[H];       // attention context
__device__ int g_tok[T];

// ---------------- init: decode tokens (int64 vs int32), zero state/out ---
__global__ void k_init(const void* __restrict__ seq_raw,
                       float* __restrict__ out, int out_size) {
    int tid = blockIdx.x * blockDim.x + threadIdx.x;
    if (tid == 0) {
        const long long* s64 = (const long long*)seq_raw;
        bool ok64 = true;
        for (int i = 0; i < T; i++) {
            long long v = s64[i];
            if (v < 0 || v >= V) { ok64 = false; break; }
        }
        const int* s32 = (const int*)seq_raw;
        for (int i = 0; i < T; i++) g_tok[i] = ok64 ? (int)s64[i] : s32[i];
    }
    int stride = gridDim.x * blockDim.x;
    for (int i = tid; i < H; i += stride) {
        g_h[0][i] = 0.f; g_c[0][i] = 0.f; g_prev[i] = 0.f;
    }
    for (int i = tid; i < out_size; i += stride) out[i] = 0.f;
}

__device__ __forceinline__ float sigm(float x) { return 1.f / (1.f + expf(-x)); }

// ---------------- encoder LSTM cell: block j -> hidden unit j ------------
__global__ void k_lstm_enc(const float* __restrict__ w_ih,
                           const float* __restrict__ w_hh,
                           const float* __restrict__ b_ih,
                           const float* __restrict__ b_hh,
                           const float* __restrict__ embeds,
                           int step, int bi) {
    int j = blockIdx.x;
    int tid = threadIdx.x;
    const float* x = embeds + (size_t)g_tok[step] * H;
    const float* hin = g_h[bi];
    const float* wi0 = w_ih + (size_t)(0 * H + j) * H;
    const float* wi1 = w_ih + (size_t)(1 * H + j) * H;
    const float* wi2 = w_ih + (size_t)(2 * H + j) * H;
    const float* wi3 = w_ih + (size_t)(3 * H + j) * H;
    const float* wh0 = w_hh + (size_t)(0 * H + j) * H;
    const float* wh1 = w_hh + (size_t)(1 * H + j) * H;
    const float* wh2 = w_hh + (size_t)(2 * H + j) * H;
    const float* wh3 = w_hh + (size_t)(3 * H + j) * H;

    float a0 = 0.f, a1 = 0.f, a2 = 0.f, a3 = 0.f;
    for (int k = tid; k < H; k += 256) {
        float xv = x[k], hv = hin[k];
        a0 += wi0[k] * xv + wh0[k] * hv;
        a1 += wi1[k] * xv + wh1[k] * hv;
        a2 += wi2[k] * xv + wh2[k] * hv;
        a3 += wi3[k] * xv + wh3[k] * hv;
    }
    __shared__ float s[4 * 256];
    s[tid] = a0; s[256 + tid] = a1; s[512 + tid] = a2; s[768 + tid] = a3;
    __syncthreads();
    for (int off = 128; off > 0; off >>= 1) {
        if (tid < off) {
            s[tid]       += s[tid + off];
            s[256 + tid] += s[256 + tid + off];
            s[512 + tid] += s[512 + tid + off];
            s[768 + tid] += s[768 + tid + off];
        }
        __syncthreads();
    }
    if (tid == 0) {
        float gi = s[0]   + b_ih[j]         + b_hh[j];
        float gf = s[256] + b_ih[H + j]     + b_hh[H + j];
        float gg = s[512] + b_ih[2 * H + j] + b_hh[2 * H + j];
        float go = s[768] + b_ih[3 * H + j] + b_hh[3 * H + j];
        float i_ = sigm(gi), f_ = sigm(gf), g_ = tanhf(gg), o_ = sigm(go);
        float cn = f_ * g_c[bi][j] + i_ * g_;
        float hn = o_ * tanhf(cn);
        g_c[1 - bi][j] = cn;
        g_h[1 - bi][j] = hn;
        g_enc[step * H + j] = hn;
    }
}

// ---------------- q = wa^T h (32 blocks x 32 cols) ------------------------
__global__ void k_q(const float* __restrict__ wa, int bi) {
    int lane = threadIdx.x & 31;
    int rg   = threadIdx.x >> 5;       // 8 row groups
    int col  = blockIdx.x * 32 + lane;
    const float* h = g_h[bi];
    float acc = 0.f;
    for (int i = rg; i < H; i += 8) acc += h[i] * wa[(size_t)i * H + col];
    __shared__ float s[256];
    s[threadIdx.x] = acc;
    __syncthreads();
    for (int off = 128; off >= 32; off >>= 1) {
        if (threadIdx.x < off) s[threadIdx.x] += s[threadIdx.x + off];
        __syncthreads();
    }
    if (threadIdx.x < 32) g_q[col] = s[threadIdx.x];
}

// ---------------- attention: scores -> softmax -> ctx (1 block) ----------
__global__ void k_attn() {
    int tid = threadIdx.x;
    float acc[T];
#pragma unroll
    for (int t = 0; t < T; t++) acc[t] = 0.f;
    for (int k = tid; k < H; k += 256) {
        float qv = g_q[k];
#pragma unroll
        for (int t = 0; t < T; t++) acc[t] += qv * g_enc[t * H + k];
    }
    __shared__ float s[T * 256];
#pragma unroll
    for (int t = 0; t < T; t++) s[t * 256 + tid] = acc[t];
    __syncthreads();
    for (int off = 128; off > 0; off >>= 1) {
        if (tid < off) {
#pragma unroll
            for (int t = 0; t < T; t++) s[t * 256 + tid] += s[t * 256 + tid + off];
        }
        __syncthreads();
    }
    __shared__ float sa[T];
    if (tid == 0) {
        float m = -INFINITY;
#pragma unroll
        for (int t = 0; t < T; t++) m = fmaxf(m, s[t * 256]);
        float sum = 0.f;
#pragma unroll
        for (int t = 0; t < T; t++) { float e = expf(s[t * 256] - m); sa[t] = e; sum += e; }
#pragma unroll
        for (int t = 0; t < T; t++) sa[t] /= sum;
    }
    __syncthreads();
    for (int k = tid; k < H; k += 256) {
        float v = 0.f;
#pragma unroll
        for (int t = 0; t < T; t++) v += sa[t] * g_enc[t * H + k];
        g_ctx[k] = v;
    }
}

// ---------------- decoder LSTM cell (x = [relu(prev), ctx], 2H) ----------
__global__ void k_lstm_dec(const float* __restrict__ w_ih,  // (4H, 2H)
                           const float* __restrict__ w_hh,  // (4H, H)
                           const float* __restrict__ b_ih,
                           const float* __restrict__ b_hh,
                           int bi) {
    int j = blockIdx.x;
    int tid = threadIdx.x;
    const float* hin = g_h[bi];
    const float* wi0 = w_ih + (size_t)(0 * H + j) * (2 * H);
    const float* wi1 = w_ih + (size_t)(1 * H + j) * (2 * H);
    const float* wi2 = w_ih + (size_t)(2 * H + j) * (2 * H);
    const float* wi3 = w_ih + (size_t)(3 * H + j) * (2 * H);
    const float* wh0 = w_hh + (size_t)(0 * H + j) * H;
    const float* wh1 = w_hh + (size_t)(1 * H + j) * H;
    const float* wh2 = w_hh + (size_t)(2 * H + j) * H;
    const float* wh3 = w_hh + (size_t)(3 * H + j) * H;

    float a0 = 0.f, a1 = 0.f, a2 = 0.f, a3 = 0.f;
    for (int k = tid; k < 2 * H; k += 256) {
        float xv = (k < H) ? fmaxf(g_prev[k], 0.f) : g_ctx[k - H];
        a0 += wi0[k] * xv;
        a1 += wi1[k] * xv;
        a2 += wi2[k] * xv;
        a3 += wi3[k] * xv;
    }
    for (int k = tid; k < H; k += 256) {
        float hv = hin[k];
        a0 += wh0[k] * hv;
        a1 += wh1[k] * hv;
        a2 += wh2[k] * hv;
        a3 += wh3[k] * hv;
    }
    __shared__ float s[4 * 256];
    s[tid] = a0; s[256 + tid] = a1; s[512 + tid] = a2; s[768 + tid] = a3;
    __syncthreads();
    for (int off = 128; off > 0; off >>= 1) {
        if (tid < off) {
            s[tid]       += s[tid + off];
            s[256 + tid] += s[256 + tid + off];
            s[512 + tid] += s[512 + tid + off];
            s[768 + tid] += s[768 + tid + off];
        }
        __syncthreads();
    }
    if (tid == 0) {
        float gi = s[0]   + b_ih[j]         + b_hh[j];
        float gf = s[256] + b_ih[H + j]     + b_hh[H + j];
        float gg = s[512] + b_ih[2 * H + j] + b_hh[2 * H + j];
        float go = s[768] + b_ih[3 * H + j] + b_hh[3 * H + j];
        float i_ = sigm(gi), f_ = sigm(gf), g_ = tanhf(gg), o_ = sigm(go);
        float cn = f_ * g_c[bi][j] + i_ * g_;
        float hn = o_ * tanhf(cn);
        g_c[1 - bi][j] = cn;
        g_h[1 - bi][j] = hn;
    }
}

// ---------------- logits: out_w @ h + out_b (4 rows/block, float4) -------
__global__ void k_logits(const float* __restrict__ out_w,
                         const float* __restrict__ out_b,
                         int hb, float* __restrict__ out) {
    int tid  = threadIdx.x;
    int rloc = tid >> 6;       // 0..3
    int lane = tid & 63;
    int r = blockIdx.x * 4 + rloc;
    float acc = 0.f;
    if (r < V) {
        const float4* wr = (const float4*)(out_w + (size_t)r * H);
        const float4* h4 = (const float4*)g_h[hb];
#pragma unroll
        for (int it = 0; it < 4; it++) {
            float4 w  = wr[lane + it * 64];
            float4 hv = h4[lane + it * 64];
            acc += w.x * hv.x + w.y * hv.y + w.z * hv.z + w.w * hv.w;
        }
    }
    for (int off = 16; off > 0; off >>= 1)
        acc += __shfl_down_sync(0xffffffffu, acc, off);
    __shared__ float s[8];
    if ((tid & 31) == 0) s[tid >> 5] = acc;
    __syncthreads();
    if (tid < 4) {
        int rr = blockIdx.x * 4 + tid;
        if (rr < V) out[rr] = s[tid * 2] + s[tid * 2 + 1] + out_b[rr];
    }
}

// ---------------- argmax (first-max, matches jnp.argmax) + gather --------
__global__ void k_argmax(const float* __restrict__ logits,
                         const float* __restrict__ embeds,
                         float* __restrict__ out_ids, int write_ids, int step) {
    int tid = threadIdx.x;
    float best = -INFINITY;
    int bidx = 0x7fffffff;
    for (int i = tid; i < V; i += 1024) {
        float v = logits[i];
        if (v > best) { best = v; bidx = i; }   // strict > keeps first occurrence
    }
    __shared__ float sv[1024];
    __shared__ int   si[1024];
    sv[tid] = best; si[tid] = bidx;
    __syncthreads();
    for (int off = 512; off > 0; off >>= 1) {
        if (tid < off) {
            float v2 = sv[tid + off]; int i2 = si[tid + off];
            if (v2 > sv[tid] || (v2 == sv[tid] && i2 < si[tid])) {
                sv[tid] = v2; si[tid] = i2;
            }
        }
        __syncthreads();
    }
    int idx = si[0];
    for (int k = tid; k < H; k += 1024)
        g_prev[k] = embeds[(size_t)idx * H + k];
    if (tid == 0 && write_ids) out_ids[step] = (float)idx;
}

// ---------------- launch ---------------------------------------------------
extern "C" void kernel_launch(void* const* d_in, const int* in_sizes, int n_in,
                              void* d_out, int out_size) {
    const void*  seq    = d_in[0];
    const float* embeds = (const float*)d_in[1];
    const float* ew_ih  = (const float*)d_in[2];
    const float* ew_hh  = (const float*)d_in[3];
    const float* eb_ih  = (const float*)d_in[4];
    const float* eb_hh  = (const float*)d_in[5];
    const float* dw_ih  = (const float*)d_in[6];
    const float* dw_hh  = (const float*)d_in[7];
    const float* db_ih  = (const float*)d_in[8];
    const float* db_hh  = (const float*)d_in[9];
    const float* out_w  = (const float*)d_in[10];
    const float* out_b  = (const float*)d_in[11];
    const float* wa     = (const float*)d_in[12];
    float* out = (float*)d_out;

    int write_ids = (out_size >= T * V + T) ? 1 : 0;

    k_init<<<256, 256>>>(seq, out, out_size);

    // encoder: step s reads buf (s&1), writes buf 1-(s&1); final h in buf 0
    for (int s = 0; s < T; s++)
        k_lstm_enc<<<H, 256>>>(ew_ih, ew_hh, eb_ih, eb_hh, embeds, s, s & 1);

    // decoder
    for (int d = 0; d < T; d++) {
        int bi = d & 1;                 // current h/c buffer
        k_q<<<32, 256>>>(wa, bi);
        k_attn<<<1, 256>>>();
        k_lstm_dec<<<H, 256>>>(dw_ih, dw_hh, db_ih, db_hh, bi);
        k_logits<<<(V + 3) / 4, 256>>>(out_w, out_b, 1 - bi, out + (size_t)d * V);
        k_argmax<<<1, 1024>>>(out + (size_t)d * V, embeds,
                              out + (size_t)T * V, write_ids, d);
    }
}

// round 2
// speedup vs baseline: 1.1810x; 1.1810x over previous
#include <cuda_runtime.h>
#include <math.h>

#define V 50257
#define H 1024
#define T 10
#define NLOGIT_BLOCKS ((V + 7) / 8)   // 6283

// ---------------- device scratch (no allocations allowed) ----------------
__device__ __align__(16) float g_h[2][H];
__device__ __align__(16) float g_c[2][H];
__device__ __align__(16) float g_enc[T * H];   // encoder outputs (T, H)
__device__ __align__(16) float g_prev[H];      // greedy feedback embedding
__device__ __align__(16) float g_q[H];         // h @ wa
__device__ __align__(16) float g_ctx[H];       // attention context
__device__ int   g_tok[T];
__device__ float g_pval[NLOGIT_BLOCKS + 32];
__device__ int   g_pidx[NLOGIT_BLOCKS + 32];
__device__ unsigned int g_cnt1;
__device__ unsigned int g_cnt2;

__device__ __forceinline__ float sigm(float x) { return 1.f / (1.f + expf(-x)); }
__device__ __forceinline__ float dot4(float4 a, float4 b) {
    return a.x * b.x + a.y * b.y + a.z * b.z + a.w * b.w;
}

// ---------------- init: decode tokens (int64 vs int32), zero state/out ---
__global__ void k_init(const void* __restrict__ seq_raw,
                       float* __restrict__ out, int out_size) {
    int tid = blockIdx.x * blockDim.x + threadIdx.x;
    if (tid == 0) {
        const long long* s64 = (const long long*)seq_raw;
        bool ok64 = true;
        for (int i = 0; i < T; i++) {
            long long v = s64[i];
            if (v < 0 || v >= V) { ok64 = false; break; }
        }
        const int* s32 = (const int*)seq_raw;
        for (int i = 0; i < T; i++) g_tok[i] = ok64 ? (int)s64[i] : s32[i];
        g_cnt1 = 0; g_cnt2 = 0;
    }
    int stride = gridDim.x * blockDim.x;
    for (int i = tid; i < H; i += stride) {
        g_h[0][i] = 0.f; g_c[0][i] = 0.f; g_prev[i] = 0.f;
    }
    for (int i = tid; i < out_size; i += stride) out[i] = 0.f;
}

// ---------------- encoder LSTM cell: block j -> hidden unit j ------------
// float4, one-shot loads: per thread 10 independent 16B loads.
__global__ void k_lstm_enc(const float* __restrict__ w_ih,
                           const float* __restrict__ w_hh,
                           const float* __restrict__ b_ih,
                           const float* __restrict__ b_hh,
                           const float* __restrict__ embeds,
                           int step, int bi) {
    int j = blockIdx.x;
    int tid = threadIdx.x;                       // 0..255, one float4 chunk
    const float4* x4 = (const float4*)(embeds + (size_t)g_tok[step] * H);
    const float4* h4 = (const float4*)g_h[bi];
    const float4* wi = (const float4*)w_ih;      // row r at wi + r*256
    const float4* wh = (const float4*)w_hh;

    float4 xv = x4[tid];
    float4 hv = h4[tid];
    float a0 = dot4(wi[(size_t)(0 * H + j) * 256 + tid], xv)
             + dot4(wh[(size_t)(0 * H + j) * 256 + tid], hv);
    float a1 = dot4(wi[(size_t)(1 * H + j) * 256 + tid], xv)
             + dot4(wh[(size_t)(1 * H + j) * 256 + tid], hv);
    float a2 = dot4(wi[(size_t)(2 * H + j) * 256 + tid], xv)
             + dot4(wh[(size_t)(2 * H + j) * 256 + tid], hv);
    float a3 = dot4(wi[(size_t)(3 * H + j) * 256 + tid], xv)
             + dot4(wh[(size_t)(3 * H + j) * 256 + tid], hv);

    __shared__ float s[4 * 256];
    s[tid] = a0; s[256 + tid] = a1; s[512 + tid] = a2; s[768 + tid] = a3;
    __syncthreads();
    for (int off = 128; off > 0; off >>= 1) {
        if (tid < off) {
            s[tid]       += s[tid + off];
            s[256 + tid] += s[256 + tid + off];
            s[512 + tid] += s[512 + tid + off];
            s[768 + tid] += s[768 + tid + off];
        }
        __syncthreads();
    }
    if (tid == 0) {
        float gi = s[0]   + b_ih[j]         + b_hh[j];
        float gf = s[256] + b_ih[H + j]     + b_hh[H + j];
        float gg = s[512] + b_ih[2 * H + j] + b_hh[2 * H + j];
        float go = s[768] + b_ih[3 * H + j] + b_hh[3 * H + j];
        float i_ = sigm(gi), f_ = sigm(gf), g_ = tanhf(gg), o_ = sigm(go);
        float cn = f_ * g_c[bi][j] + i_ * g_;
        float hn = o_ * tanhf(cn);
        g_c[1 - bi][j] = cn;
        g_h[1 - bi][j] = hn;
        g_enc[step * H + j] = hn;
    }
}

// ---------------- q = wa^T h, then last block does softmax+ctx -----------
__global__ void k_qattn(const float* __restrict__ wa, int bi) {
    int tid  = threadIdx.x;
    int lane = tid & 31;
    int warp = tid >> 5;        // 8 row groups
    int col  = blockIdx.x * 32 + lane;
    const float* h = g_h[bi];

    float acc = 0.f;
    for (int i = warp; i < H; i += 8) acc += h[i] * wa[(size_t)i * H + col];
    __shared__ float s[256];
    s[tid] = acc;
    __syncthreads();
    for (int off = 128; off >= 32; off >>= 1) {
        if (tid < off) s[tid] += s[tid + off];
        __syncthreads();
    }
    if (tid < 32) g_q[col] = s[tid];

    // -------- last-block-done: attention ----------
    __shared__ int s_last;
    __threadfence();
    if (tid == 0) s_last = (atomicAdd(&g_cnt1, 1u) == gridDim.x - 1);
    __syncthreads();
    if (!s_last) return;
    if (tid == 0) g_cnt1 = 0;

    float at[T];
#pragma unroll
    for (int t = 0; t < T; t++) at[t] = 0.f;
    for (int k = tid; k < H; k += 256) {
        float qv = g_q[k];
#pragma unroll
        for (int t = 0; t < T; t++) at[t] += qv * g_enc[t * H + k];
    }
#pragma unroll
    for (int t = 0; t < T; t++)
        for (int off = 16; off > 0; off >>= 1)
            at[t] += __shfl_down_sync(0xffffffffu, at[t], off);
    __shared__ float s2[T * 8];
    if (lane == 0) {
#pragma unroll
        for (int t = 0; t < T; t++) s2[t * 8 + warp] = at[t];
    }
    __syncthreads();
    __shared__ float sa[T];
    if (tid == 0) {
        float sc[T];
        float m = -INFINITY;
#pragma unroll
        for (int t = 0; t < T; t++) {
            float v = 0.f;
#pragma unroll
            for (int w = 0; w < 8; w++) v += s2[t * 8 + w];
            sc[t] = v;
            m = fmaxf(m, v);
        }
        float sum = 0.f;
#pragma unroll
        for (int t = 0; t < T; t++) { float e = expf(sc[t] - m); sa[t] = e; sum += e; }
#pragma unroll
        for (int t = 0; t < T; t++) sa[t] /= sum;
    }
    __syncthreads();
    for (int k = tid; k < H; k += 256) {
        float v = 0.f;
#pragma unroll
        for (int t = 0; t < T; t++) v += sa[t] * g_enc[t * H + k];
        g_ctx[k] = v;
    }
}

// ---------------- decoder LSTM cell (x = [relu(prev), ctx], 2H) ----------
__global__ void k_lstm_dec(const float* __restrict__ w_ih,  // (4H, 2H)
                           const float* __restrict__ w_hh,  // (4H, H)
                           const float* __restrict__ b_ih,
                           const float* __restrict__ b_hh,
                           int bi) {
    int j = blockIdx.x;
    int tid = threadIdx.x;
    const float4* h4 = (const float4*)g_h[bi];
    const float4* p4 = (const float4*)g_prev;
    const float4* c4 = (const float4*)g_ctx;
    const float4* wi = (const float4*)w_ih;   // row r: 512 float4
    const float4* wh = (const float4*)w_hh;   // row r: 256 float4

    float4 xa = p4[tid];
    xa.x = fmaxf(xa.x, 0.f); xa.y = fmaxf(xa.y, 0.f);
    xa.z = fmaxf(xa.z, 0.f); xa.w = fmaxf(xa.w, 0.f);
    float4 xb = c4[tid];
    float4 hv = h4[tid];

    float a0 = dot4(wi[(size_t)(0 * H + j) * 512 + tid], xa)
             + dot4(wi[(size_t)(0 * H + j) * 512 + 256 + tid], xb)
             + dot4(wh[(size_t)(0 * H + j) * 256 + tid], hv);
    float a1 = dot4(wi[(size_t)(1 * H + j) * 512 + tid], xa)
             + dot4(wi[(size_t)(1 * H + j) * 512 + 256 + tid], xb)
             + dot4(wh[(size_t)(1 * H + j) * 256 + tid], hv);
    float a2 = dot4(wi[(size_t)(2 * H + j) * 512 + tid], xa)
             + dot4(wi[(size_t)(2 * H + j) * 512 + 256 + tid], xb)
             + dot4(wh[(size_t)(2 * H + j) * 256 + tid], hv);
    float a3 = dot4(wi[(size_t)(3 * H + j) * 512 + tid], xa)
             + dot4(wi[(size_t)(3 * H + j) * 512 + 256 + tid], xb)
             + dot4(wh[(size_t)(3 * H + j) * 256 + tid], hv);

    __shared__ float s[4 * 256];
    s[tid] = a0; s[256 + tid] = a1; s[512 + tid] = a2; s[768 + tid] = a3;
    __syncthreads();
    for (int off = 128; off > 0; off >>= 1) {
        if (tid < off) {
            s[tid]       += s[tid + off];
            s[256 + tid] += s[256 + tid + off];
            s[512 + tid] += s[512 + tid + off];
            s[768 + tid] += s[768 + tid + off];
        }
        __syncthreads();
    }
    if (tid == 0) {
        float gi = s[0]   + b_ih[j]         + b_hh[j];
        float gf = s[256] + b_ih[H + j]     + b_hh[H + j];
        float gg = s[512] + b_ih[2 * H + j] + b_hh[2 * H + j];
        float go = s[768] + b_ih[3 * H + j] + b_hh[3 * H + j];
        float i_ = sigm(gi), f_ = sigm(gf), g_ = tanhf(gg), o_ = sigm(go);
        float cn = f_ * g_c[bi][j] + i_ * g_;
        float hn = o_ * tanhf(cn);
        g_c[1 - bi][j] = cn;
        g_h[1 - bi][j] = hn;
    }
}

// ---------------- logits (warp-per-row, __ldcs stream) + fused argmax ----
__global__ void k_logits(const float* __restrict__ out_w,
                         const float* __restrict__ out_b,
                         int hb, float* __restrict__ out,
                         const float* __restrict__ embeds,
                         float* __restrict__ out_ids, int write_ids, int step) {
    int tid  = threadIdx.x;
    int lane = tid & 31;
    int warp = tid >> 5;                 // 8 warps, one row each
    int r = blockIdx.x * 8 + warp;

    float logit = -INFINITY;
    if (r < V) {
        const float4* wr = (const float4*)(out_w + (size_t)r * H);
        const float4* h4 = (const float4*)g_h[hb];
        float acc[8];
#pragma unroll
        for (int i = 0; i < 8; i++) {
            float4 w  = __ldcs(wr + lane + 32 * i);   // evict-first: protect L2
            float4 hv = h4[lane + 32 * i];
            acc[i] = dot4(w, hv);
        }
        float tot = ((acc[0] + acc[1]) + (acc[2] + acc[3]))
                  + ((acc[4] + acc[5]) + (acc[6] + acc[7]));
        for (int off = 16; off > 0; off >>= 1)
            tot += __shfl_down_sync(0xffffffffu, tot, off);
        if (lane == 0) {
            logit = tot + out_b[r];
            out[r] = logit;
        }
    }

    // -------- per-block argmax over 8 rows ----------
    __shared__ float bv[8];
    __shared__ int   bix[8];
    __shared__ int   s_last;
    if (lane == 0) { bv[warp] = (r < V) ? logit : -INFINITY; bix[warp] = r; }
    __syncthreads();
    if (tid == 0) {
        float best = bv[0]; int bj = bix[0];
        for (int w = 1; w < 8; w++)
            if (bv[w] > best) { best = bv[w]; bj = bix[w]; }
        g_pval[blockIdx.x] = best;
        g_pidx[blockIdx.x] = bj;
        __threadfence();
        s_last = (atomicAdd(&g_cnt2, 1u) == gridDim.x - 1);
    }
    __syncthreads();
    if (!s_last) return;
    if (tid == 0) g_cnt2 = 0;

    // -------- final argmax (first-max, matches jnp.argmax) + gather ------
    float best = -INFINITY;
    int bidx = 0x7fffffff;
    int nb = gridDim.x;
    for (int i = tid; i < nb; i += 256) {
        float v = g_pval[i]; int ix = g_pidx[i];
        if (v > best || (v == best && ix < bidx)) { best = v; bidx = ix; }
    }
    __shared__ float sv[256];
    __shared__ int   si[256];
    sv[tid] = best; si[tid] = bidx;
    __syncthreads();
    for (int off = 128; off > 0; off >>= 1) {
        if (tid < off) {
            float v2 = sv[tid + off]; int i2 = si[tid + off];
            if (v2 > sv[tid] || (v2 == sv[tid] && i2 < si[tid])) {
                sv[tid] = v2; si[tid] = i2;
            }
        }
        __syncthreads();
    }
    int idx = si[0];
    for (int k = tid; k < H; k += 256)
        g_prev[k] = embeds[(size_t)idx * H + k];
    if (tid == 0 && write_ids) out_ids[step] = (float)idx;
}

// ---------------- launch ---------------------------------------------------
extern "C" void kernel_launch(void* const* d_in, const int* in_sizes, int n_in,
                              void* d_out, int out_size) {
    const void*  seq    = d_in[0];
    const float* embeds = (const float*)d_in[1];
    const float* ew_ih  = (const float*)d_in[2];
    const float* ew_hh  = (const float*)d_in[3];
    const float* eb_ih  = (const float*)d_in[4];
    const float* eb_hh  = (const float*)d_in[5];
    const float* dw_ih  = (const float*)d_in[6];
    const float* dw_hh  = (const float*)d_in[7];
    const float* db_ih  = (const float*)d_in[8];
    const float* db_hh  = (const float*)d_in[9];
    const float* out_w  = (const float*)d_in[10];
    const float* out_b  = (const float*)d_in[11];
    const float* wa     = (const float*)d_in[12];
    float* out = (float*)d_out;

    int write_ids = (out_size >= T * V + T) ? 1 : 0;

    k_init<<<256, 256>>>(seq, out, out_size);

    // encoder: step s reads buf (s&1), writes buf 1-(s&1); final h in buf 0
    for (int s = 0; s < T; s++)
        k_lstm_enc<<<H, 256>>>(ew_ih, ew_hh, eb_ih, eb_hh, embeds, s, s & 1);

    // decoder
    for (int d = 0; d < T; d++) {
        int bi = d & 1;                 // current h/c buffer
        k_qattn<<<32, 256>>>(wa, bi);
        k_lstm_dec<<<H, 256>>>(dw_ih, dw_hh, db_ih, db_hh, bi);
        k_logits<<<NLOGIT_BLOCKS, 256>>>(out_w, out_b, 1 - bi,
                                         out + (size_t)d * V,
                                         embeds, out + (size_t)T * V,
                                         write_ids, d);
    }
}

// round 3
// speedup vs baseline: 1.5366x; 1.3011x over previous
#include <cuda_runtime.h>
#include <math.h>

#define V 50257
#define H 1024
#define T 10
#define LOGIT_ROWS_PER_BLOCK 16
#define NLOGIT_BLOCKS ((V + LOGIT_ROWS_PER_BLOCK - 1) / LOGIT_ROWS_PER_BLOCK)  // 3142

// ---------------- device scratch (no allocations allowed) ----------------
__device__ __align__(16) float g_h[2][H];
__device__ __align__(16) float g_c[2][H];
__device__ __align__(16) float g_enc[T * H];   // encoder outputs (T, H)
__device__ __align__(16) float g_prev[H];      // greedy feedback embedding
__device__ __align__(16) float g_q[H];         // h @ wa
__device__ __align__(16) float g_ctx[H];       // attention context
__device__ int   g_tok[T];
__device__ float g_pval[NLOGIT_BLOCKS + 32];
__device__ int   g_pidx[NLOGIT_BLOCKS + 32];
__device__ unsigned int g_cnt1;
__device__ unsigned int g_cnt2;

__device__ __forceinline__ float sigm(float x) { return 1.f / (1.f + expf(-x)); }
__device__ __forceinline__ float dot4(float4 a, float4 b) {
    return a.x * b.x + a.y * b.y + a.z * b.z + a.w * b.w;
}

// ---------------- init: decode tokens (int64 vs int32), zero state/out ---
__global__ void k_init(const void* __restrict__ seq_raw,
                       float* __restrict__ out, int out_size) {
    int tid = blockIdx.x * blockDim.x + threadIdx.x;
    if (tid == 0) {
        const long long* s64 = (const long long*)seq_raw;
        bool ok64 = true;
        for (int i = 0; i < T; i++) {
            long long v = s64[i];
            if (v < 0 || v >= V) { ok64 = false; break; }
        }
        const int* s32 = (const int*)seq_raw;
        for (int i = 0; i < T; i++) g_tok[i] = ok64 ? (int)s64[i] : s32[i];
        g_cnt1 = 0; g_cnt2 = 0;
    }
    int stride = gridDim.x * blockDim.x;
    for (int i = tid; i < H; i += stride) {
        g_h[0][i] = 0.f; g_c[0][i] = 0.f; g_prev[i] = 0.f;
    }
    for (int i = tid; i < out_size; i += stride) out[i] = 0.f;
}

// ---------------- encoder LSTM: 2 units/block, warp-per-gate -------------
// warp = (unit_local<<2)|gate; lane covers 8 float4 of w_ih row + 8 of w_hh.
__global__ void k_lstm_enc(const float* __restrict__ w_ih,
                           const float* __restrict__ w_hh,
                           const float* __restrict__ b_ih,
                           const float* __restrict__ b_hh,
                           const float* __restrict__ embeds,
                           int step, int bi) {
    int tid  = threadIdx.x;
    int warp = tid >> 5;
    int lane = tid & 31;
    int j    = blockIdx.x * 2 + (warp >> 2);
    int gate = warp & 3;

    const float4* x4 = (const float4*)(embeds + (size_t)g_tok[step] * H);
    const float4* h4 = (const float4*)g_h[bi];
    const float4* wi = (const float4*)w_ih + (size_t)(gate * H + j) * 256;
    const float4* wh = (const float4*)w_hh + (size_t)(gate * H + j) * 256;

    float acc = 0.f;
#pragma unroll
    for (int i = 0; i < 8; i++) {
        int k = lane + 32 * i;
        acc += dot4(wi[k], x4[k]) + dot4(wh[k], h4[k]);
    }
    for (int off = 16; off > 0; off >>= 1)
        acc += __shfl_down_sync(0xffffffffu, acc, off);

    __shared__ float s[8];
    if (lane == 0) s[warp] = acc;
    __syncthreads();
    if (tid < 2) {
        int u = blockIdx.x * 2 + tid;
        float gi = s[tid * 4 + 0] + b_ih[u]         + b_hh[u];
        float gf = s[tid * 4 + 1] + b_ih[H + u]     + b_hh[H + u];
        float gg = s[tid * 4 + 2] + b_ih[2 * H + u] + b_hh[2 * H + u];
        float go = s[tid * 4 + 3] + b_ih[3 * H + u] + b_hh[3 * H + u];
        float i_ = sigm(gi), f_ = sigm(gf), g_ = tanhf(gg), o_ = sigm(go);
        float cn = f_ * g_c[bi][u] + i_ * g_;
        float hn = o_ * tanhf(cn);
        g_c[1 - bi][u] = cn;
        g_h[1 - bi][u] = hn;
        g_enc[step * H + u] = hn;
    }
}

// ---------------- q = wa^T h, then last block does softmax+ctx -----------
__global__ void k_qattn(const float* __restrict__ wa, int bi) {
    int tid  = threadIdx.x;
    int lane = tid & 31;
    int warp = tid >> 5;        // 8 row groups
    int col  = blockIdx.x * 32 + lane;
    const float* h = g_h[bi];

    float acc = 0.f;
    for (int i = warp; i < H; i += 8) acc += h[i] * wa[(size_t)i * H + col];
    __shared__ float s[256];
    s[tid] = acc;
    __syncthreads();
    for (int off = 128; off >= 32; off >>= 1) {
        if (tid < off) s[tid] += s[tid + off];
        __syncthreads();
    }
    if (tid < 32) g_q[col] = s[tid];

    // -------- last-block-done: attention ----------
    __shared__ int s_last;
    __threadfence();
    if (tid == 0) s_last = (atomicAdd(&g_cnt1, 1u) == gridDim.x - 1);
    __syncthreads();
    if (!s_last) return;
    if (tid == 0) g_cnt1 = 0;

    float at[T];
#pragma unroll
    for (int t = 0; t < T; t++) at[t] = 0.f;
    for (int k = tid; k < H; k += 256) {
        float qv = g_q[k];
#pragma unroll
        for (int t = 0; t < T; t++) at[t] += qv * g_enc[t * H + k];
    }
#pragma unroll
    for (int t = 0; t < T; t++)
        for (int off = 16; off > 0; off >>= 1)
            at[t] += __shfl_down_sync(0xffffffffu, at[t], off);
    __shared__ float s2[T * 8];
    if (lane == 0) {
#pragma unroll
        for (int t = 0; t < T; t++) s2[t * 8 + warp] = at[t];
    }
    __syncthreads();
    __shared__ float sa[T];
    if (tid == 0) {
        float sc[T];
        float m = -INFINITY;
#pragma unroll
        for (int t = 0; t < T; t++) {
            float v = 0.f;
#pragma unroll
            for (int w = 0; w < 8; w++) v += s2[t * 8 + w];
            sc[t] = v;
            m = fmaxf(m, v);
        }
        float sum = 0.f;
#pragma unroll
        for (int t = 0; t < T; t++) { float e = expf(sc[t] - m); sa[t] = e; sum += e; }
#pragma unroll
        for (int t = 0; t < T; t++) sa[t] /= sum;
    }
    __syncthreads();
    for (int k = tid; k < H; k += 256) {
        float v = 0.f;
#pragma unroll
        for (int t = 0; t < T; t++) v += sa[t] * g_enc[t * H + k];
        g_ctx[k] = v;
    }
}

// ---------------- decoder LSTM: 2 units/block, warp-per-gate -------------
__global__ void k_lstm_dec(const float* __restrict__ w_ih,  // (4H, 2H)
                           const float* __restrict__ w_hh,  // (4H, H)
                           const float* __restrict__ b_ih,
                           const float* __restrict__ b_hh,
                           int bi) {
    int tid  = threadIdx.x;
    int warp = tid >> 5;
    int lane = tid & 31;
    int j    = blockIdx.x * 2 + (warp >> 2);
    int gate = warp & 3;

    const float4* h4 = (const float4*)g_h[bi];
    const float4* p4 = (const float4*)g_prev;
    const float4* c4 = (const float4*)g_ctx;
    const float4* wi = (const float4*)w_ih + (size_t)(gate * H + j) * 512;
    const float4* wh = (const float4*)w_hh + (size_t)(gate * H + j) * 256;

    float acc = 0.f;
#pragma unroll
    for (int i = 0; i < 8; i++) {
        int k = lane + 32 * i;
        float4 xa = p4[k];
        xa.x = fmaxf(xa.x, 0.f); xa.y = fmaxf(xa.y, 0.f);
        xa.z = fmaxf(xa.z, 0.f); xa.w = fmaxf(xa.w, 0.f);
        acc += dot4(wi[k], xa);
        acc += dot4(wi[256 + k], c4[k]);
        acc += dot4(wh[k], h4[k]);
    }
    for (int off = 16; off > 0; off >>= 1)
        acc += __shfl_down_sync(0xffffffffu, acc, off);

    __shared__ float s[8];
    if (lane == 0) s[warp] = acc;
    __syncthreads();
    if (tid < 2) {
        int u = blockIdx.x * 2 + tid;
        float gi = s[tid * 4 + 0] + b_ih[u]         + b_hh[u];
        float gf = s[tid * 4 + 1] + b_ih[H + u]     + b_hh[H + u];
        float gg = s[tid * 4 + 2] + b_ih[2 * H + u] + b_hh[2 * H + u];
        float go = s[tid * 4 + 3] + b_ih[3 * H + u] + b_hh[3 * H + u];
        float i_ = sigm(gi), f_ = sigm(gf), g_ = tanhf(gg), o_ = sigm(go);
        float cn = f_ * g_c[bi][u] + i_ * g_;
        float hn = o_ * tanhf(cn);
        g_c[1 - bi][u] = cn;
        g_h[1 - bi][u] = hn;
    }
}

// ---------------- logits: 2 rows per warp, __ldcs stream, fused argmax ---
__global__ void k_logits(const float* __restrict__ out_w,
                         const float* __restrict__ out_b,
                         int hb, float* __restrict__ out,
                         const float* __restrict__ embeds,
                         float* __restrict__ out_ids, int write_ids, int step) {
    int tid  = threadIdx.x;
    int lane = tid & 31;
    int warp = tid >> 5;                 // 8 warps, 2 rows each
    int r0 = blockIdx.x * LOGIT_ROWS_PER_BLOCK + warp * 2;
    int r1 = r0 + 1;

    const float4* h4 = (const float4*)g_h[hb];
    float4 hv[8];
#pragma unroll
    for (int i = 0; i < 8; i++) hv[i] = h4[lane + 32 * i];

    float t0 = 0.f, t1 = 0.f;
    if (r0 < V) {
        const float4* w0 = (const float4*)(out_w + (size_t)r0 * H);
#pragma unroll
        for (int i = 0; i < 8; i++) t0 += dot4(__ldcs(w0 + lane + 32 * i), hv[i]);
    }
    if (r1 < V) {
        const float4* w1 = (const float4*)(out_w + (size_t)r1 * H);
#pragma unroll
        for (int i = 0; i < 8; i++) t1 += dot4(__ldcs(w1 + lane + 32 * i), hv[i]);
    }
    for (int off = 16; off > 0; off >>= 1) {
        t0 += __shfl_down_sync(0xffffffffu, t0, off);
        t1 += __shfl_down_sync(0xffffffffu, t1, off);
    }

    __shared__ float bv[16];
    __shared__ int   bix[16];
    __shared__ int   s_last;
    if (lane == 0) {
        float l0 = -INFINITY, l1 = -INFINITY;
        if (r0 < V) { l0 = t0 + out_b[r0]; __stcs(out + r0, l0); }
        if (r1 < V) { l1 = t1 + out_b[r1]; __stcs(out + r1, l1); }
        bv[warp * 2] = l0;     bix[warp * 2] = r0;
        bv[warp * 2 + 1] = l1; bix[warp * 2 + 1] = r1;
    }
    __syncthreads();
    if (tid == 0) {
        float best = bv[0]; int bj = bix[0];
#pragma unroll
        for (int w = 1; w < 16; w++)
            if (bv[w] > best) { best = bv[w]; bj = bix[w]; }
        g_pval[blockIdx.x] = best;
        g_pidx[blockIdx.x] = bj;
        __threadfence();
        s_last = (atomicAdd(&g_cnt2, 1u) == gridDim.x - 1);
    }
    __syncthreads();
    if (!s_last) return;
    if (tid == 0) g_cnt2 = 0;

    // -------- final argmax (first-max, matches jnp.argmax) + gather ------
    float best = -INFINITY;
    int bidx = 0x7fffffff;
    int nb = gridDim.x;
    for (int i = tid; i < nb; i += 256) {
        float v = g_pval[i]; int ix = g_pidx[i];
        if (v > best || (v == best && ix < bidx)) { best = v; bidx = ix; }
    }
    __shared__ float sv[256];
    __shared__ int   si[256];
    sv[tid] = best; si[tid] = bidx;
    __syncthreads();
    for (int off = 128; off > 0; off >>= 1) {
        if (tid < off) {
            float v2 = sv[tid + off]; int i2 = si[tid + off];
            if (v2 > sv[tid] || (v2 == sv[tid] && i2 < si[tid])) {
                sv[tid] = v2; si[tid] = i2;
            }
        }
        __syncthreads();
    }
    int idx = si[0];
    for (int k = tid; k < H; k += 256)
        g_prev[k] = embeds[(size_t)idx * H + k];
    if (tid == 0 && write_ids) out_ids[step] = (float)idx;
}

// ---------------- launch ---------------------------------------------------
extern "C" void kernel_launch(void* const* d_in, const int* in_sizes, int n_in,
                              void* d_out, int out_size) {
    const void*  seq    = d_in[0];
    const float* embeds = (const float*)d_in[1];
    const float* ew_ih  = (const float*)d_in[2];
    const float* ew_hh  = (const float*)d_in[3];
    const float* eb_ih  = (const float*)d_in[4];
    const float* eb_hh  = (const float*)d_in[5];
    const float* dw_ih  = (const float*)d_in[6];
    const float* dw_hh  = (const float*)d_in[7];
    const float* db_ih  = (const float*)d_in[8];
    const float* db_hh  = (const float*)d_in[9];
    const float* out_w  = (const float*)d_in[10];
    const float* out_b  = (const float*)d_in[11];
    const float* wa     = (const float*)d_in[12];
    float* out = (float*)d_out;

    int write_ids = (out_size >= T * V + T) ? 1 : 0;

    // Side stream + events created once, on the (non-captured) correctness
    // call; reused as graph fork/join dependencies during capture.
    static cudaStream_t s2 = nullptr;
    static cudaEvent_t evFork = nullptr, evJoin = nullptr;
    if (!s2) {
        cudaStreamCreateWithFlags(&s2, cudaStreamNonBlocking);
        cudaEventCreateWithFlags(&evFork, cudaEventDisableTiming);
        cudaEventCreateWithFlags(&evJoin, cudaEventDisableTiming);
    }

    k_init<<<256, 256>>>(seq, out, out_size);

    // encoder: step s reads buf (s&1), writes buf 1-(s&1); final h in buf 0
    for (int s = 0; s < T; s++)
        k_lstm_enc<<<H / 2, 256>>>(ew_ih, ew_hh, eb_ih, eb_hh, embeds, s, s & 1);

    // decoder; qattn(d+1) overlaps logits(d) on side stream
    k_qattn<<<32, 256>>>(wa, 0);
    for (int d = 0; d < T; d++) {
        int bi = d & 1;                 // current h/c buffer
        k_lstm_dec<<<H / 2, 256>>>(dw_ih, dw_hh, db_ih, db_hh, bi);
        if (d + 1 < T) {
            cudaEventRecord(evFork, 0);
            cudaStreamWaitEvent(s2, evFork, 0);
            k_qattn<<<32, 256, 0, s2>>>(wa, (d + 1) & 1);
            cudaEventRecord(evJoin, s2);
        }
        k_logits<<<NLOGIT_BLOCKS, 256>>>(out_w, out_b, 1 - bi,
                                         out + (size_t)d * V,
                                         embeds, out + (size_t)T * V,
                                         write_ids, d);
        if (d + 1 < T) cudaStreamWaitEvent(0, evJoin, 0);
    }
}